// round 14
// baseline (speedup 1.0000x reference)
#include <cuda_runtime.h>
#include <math.h>
#include <float.h>

#define TPB    1024
#define KNN_K  16
#define NBUCK  64
#define FULLM  0xFFFFFFFFu
#define XMIN   (-4.8f)
#define XMAX   ( 4.8f)
#define BW     ((XMAX - XMIN) / (float)NBUCK)
#define INVBW  ((float)NBUCK / (XMAX - XMIN))
#define SAFE   1e-5f
#define FPRE   4          // rows each KNN block zero-fills before spinning

// scratch (static device arrays; allocation-free rule)
__device__ int                g_idx [65536 * KNN_K];
__device__ float              g_w   [65536 * KNN_K];
__device__ float              g_Dfwd[65536];
__device__ unsigned long long g_Drev[65536];
__device__ float              g_dis [65536];         // D^{-1/2} per node

__device__ int            g_off [16 * (NBUCK + 1)];
__device__ float4         g_rc  [65536];             // reordered (x,y,z,|p|^2)
__device__ unsigned short g_rid [65536];             // orig index per position
__device__ int            g_ready;                   // bucket-done counter (k_lap resets)
__device__ int            g_knn_done;                // knn-blocks-retired counter (k_lap resets)

__device__ __forceinline__ int bucket_of_x(float x) {
    int ib = (int)((x - XMIN) * INVBW);
    return min(max(ib, 0), NBUCK - 1);
}

// zero one row + diagonal patch (lean streaming stores)
__device__ __forceinline__ void fill_row(float* __restrict__ out, int N, int r, int tid)
{
    const float4 z4 = make_float4(0.0f, 0.0f, 0.0f, 0.0f);
    int n4 = N >> 2;
    int b = r / N;
    int i = r - b * N;
    float4* row = reinterpret_cast<float4*>(out + ((size_t)b * N + i) * (size_t)N);
    #pragma unroll 2
    for (int f = tid; f < n4; f += TPB)
        __stcs(row + f, z4);
    int fd = i >> 2;
    if (tid == (fd & (TPB - 1))) {          // same thread re-writes same addr: ordered
        float4 v = z4;
        ((float*)&v)[i & 3] = 1.0f;
        __stcs(row + fd, v);
    }
}

// ---------- fused bucket + KNN + dense init ----------
// bids [0, B):              bucket prepass (hist+scan+reorder+Drev zero), flag arrive
// bids [B, B+nb_knn):       KNN (prefill FPRE rows, spin on flag, then knn);
//                           the LAST knn block to retire computes g_dis.
// bids [B+nb_knn, ...):     zero-fill remaining rows (grid-stride)
__global__ void __launch_bounds__(TPB, 2)
k_fused(const float* __restrict__ xyz, float* __restrict__ out,
        int N, int B, int nb_knn, int nb_ms)
{
    extern __shared__ char smraw[];
    const int tid = threadIdx.x;
    const int bid = blockIdx.x;

    if (bid < B) {
        // ---------------- bucket prepass (one batch per block) ------------
        int* h   = reinterpret_cast<int*>(smraw);
        int* cur = h + NBUCK;
        const int b = bid;
        const int bN = b * N;
        const float* X = xyz + (size_t)b * 3 * N;

        if (tid < NBUCK) h[tid] = 0;
        __syncthreads();
        for (int n = tid; n < N; n += TPB) {
            g_Drev[bN + n] = 0ull;          // pre-zero for knn epilogue atomics
            atomicAdd(&h[bucket_of_x(X[n])], 1);
        }
        __syncthreads();
        if (tid < 32) {                     // warp 0: scan 64 counts
            int v0 = h[tid], v1 = h[tid + 32];
            int s0 = v0, s1 = v1;
            for (int d = 1; d < 32; d <<= 1) {
                int t0 = __shfl_up_sync(FULLM, s0, d);
                int t1 = __shfl_up_sync(FULLM, s1, d);
                if (tid >= d) { s0 += t0; s1 += t1; }
            }
            s1 += __shfl_sync(FULLM, s0, 31);
            int ob = b * (NBUCK + 1);
            if (tid == 0) g_off[ob] = 0;
            g_off[ob + 1 + tid]  = s0;
            g_off[ob + 33 + tid] = s1;
            cur[tid]      = s0 - v0;
            cur[tid + 32] = s1 - v1;
        }
        __syncthreads();
        for (int n = tid; n < N; n += TPB) {
            float x = X[n], y = X[N + n], z = X[2 * N + n];
            float sq = fmaf(x, x, fmaf(y, y, z * z));
            int pos = atomicAdd(&cur[bucket_of_x(x)], 1);
            g_rc [bN + pos] = make_float4(x, y, z, sq);
            g_rid[bN + pos] = (unsigned short)n;
        }
        __threadfence();
        __syncthreads();
        if (tid == 0) atomicAdd(&g_ready, 1);
        return;
    }

    if (bid >= B + nb_knn) {
        // ------------- zero-fill remaining rows (grid-stride) -------------
        int msid  = bid - B - nb_knn;
        int nrows = B * N;
        for (int r = nb_knn * FPRE + msid; r < nrows; r += nb_ms)
            fill_row(out, N, r, tid);
        return;
    }

    // ---------------- KNN role ----------------
    const int kb = bid - B;                     // 0 .. nb_knn-1

    // useful work while bucket prepass runs: prefill FPRE rows
    for (int r = kb * FPRE; r < kb * FPRE + FPRE; r++)
        fill_row(out, N, r, tid);

    // wait for bucket flag (bucket blocks have lower bids => wave-1 resident)
    if (tid == 0) {
        while (atomicAdd(&g_ready, 0) < B) __nanosleep(64);
    }
    __syncthreads();
    __threadfence();

    float4*         rc  = reinterpret_cast<float4*>(smraw);            // N float4
    unsigned short* rid = reinterpret_cast<unsigned short*>(rc + N);   // N ushort
    int*            off = reinterpret_cast<int*>(rid + N);             // NBUCK+1
    __shared__ int  s_last;

    const int qpb = (TPB / 32) * 2;             // 64 queries per block
    const int blocks_per_b = N / qpb;
    const int b = kb / blocks_per_b;
    const int qbase = (kb - b * blocks_per_b) * qpb;
    const int bN = b * N;

    for (int n = tid; n < N; n += TPB) rc[n]  = g_rc[bN + n];
    for (int n = tid; n < N; n += TPB) rid[n] = g_rid[bN + n];
    if (tid <= NBUCK) off[tid] = g_off[b * (NBUCK + 1) + tid];
    __syncthreads();

    const int warp = tid >> 5, lane = tid & 31;
    const int g = lane >> 4, sub = lane & 15;
    const int pos0 = qbase + warp * 2;          // bucket-sorted positions

    // queries kept ONLY in pre-scaled form to save registers: a = -2q, qw=|q|^2
    float a0x, a0y, a0z, q0w, a1x, a1y, a1z, q1w;
    {
        float4 q0 = rc[pos0];
        float4 q1 = rc[pos0 + 1];
        a0x = -2.0f * q0.x; a0y = -2.0f * q0.y; a0z = -2.0f * q0.z; q0w = q0.w;
        a1x = -2.0f * q1.x; a1y = -2.0f * q1.y; a1z = -2.0f * q1.z; q1w = q1.w;
    }

    // density-seeded screening thresholds in e-space (~40 expected pts in ball)
    const float seed0 = 0.1107f * __expf(q0w * (1.0f / 3.0f)) - q0w;
    const float seed1 = 0.1107f * __expf(q1w * (1.0f / 3.0f)) - q1w;

    // sorted-across-lanes top-16 in e-space; li = POSITION in rc
    float ld = FLT_MAX; int li = 0;
    float wt0, wt1;

    auto process = [&](int start, int end) {
        for (int p = start; p < end; p += 32) {
            int pp = p + lane;
            bool valid = pp < end;
            float4 c = rc[valid ? pp : end - 1];
            float e0 = fmaf(a0x, c.x, fmaf(a0y, c.y, fmaf(a0z, c.z, c.w)));
            float e1 = fmaf(a1x, c.x, fmaf(a1y, c.y, fmaf(a1z, c.z, c.w)));
            unsigned bal0 = __ballot_sync(FULLM, valid && (e0 < wt0));
            unsigned bal1 = __ballot_sync(FULLM, valid && (e1 < wt1));
            if ((bal0 | bal1) == 0u) continue;
            do {
                int s0 = __ffs(bal0) - 1;
                int s1 = __ffs(bal1) - 1;
                float dd0 = __shfl_sync(FULLM, e0, s0 & 31);
                float dd1 = __shfl_sync(FULLM, e1, s1 & 31);
                bool have = g ? (bal1 != 0u) : (bal0 != 0u);
                float dd = g ? dd1 : dd0;
                int   jj = p + ((g ? s1 : s0) & 31);
                bool pr = have && (dd < ld);
                unsigned pb = __ballot_sync(FULLM, pr);
                float sld = __shfl_up_sync(FULLM, ld, 1);
                int   sli = __shfl_up_sync(FULLM, li, 1);
                bool prevpr = (sub > 0) && ((pb >> (lane - 1)) & 1u);
                if (pr) { ld = prevpr ? sld : dd; li = prevpr ? sli : jj; }
                bal0 &= bal0 - 1;
                bal1 &= bal1 - 1;
            } while (bal0 | bal1);
            // monotone non-increasing thresholds (min with seed when underfull)
            wt0 = fminf(wt0, __shfl_sync(FULLM, ld, 15));
            wt1 = fminf(wt1, __shfl_sync(FULLM, ld, 31));
        }
    };

    // home buckets of the two queries (binary search over off[], warp-uniform)
    int hlo, hhi;
    {
        int lo = 0, hi = NBUCK - 1;
        while (lo < hi) { int mid = (lo + hi + 1) >> 1; if (off[mid] <= pos0) lo = mid; else hi = mid - 1; }
        hlo = lo;
        lo = hlo; hi = NBUCK - 1;
        int p1 = pos0 + 1;
        while (lo < hi) { int mid = (lo + hi + 1) >> 1; if (off[mid] <= p1) lo = mid; else hi = mid - 1; }
        hhi = lo;
    }

    for (int attempt = 0; attempt < 2; attempt++) {
        ld = FLT_MAX; li = 0;
        wt0 = attempt ? FLT_MAX : seed0;
        wt1 = attempt ? FLT_MAX : seed1;
        int blo = hlo, bhi = hhi;

        process(off[blo], off[bhi + 1]);

        bool leftOpen = blo > 0, rightOpen = bhi < NBUCK - 1;
        while (leftOpen || rightOpen) {
            float qx0 = -0.5f * a0x, qx1 = -0.5f * a1x;
            float r20 = (wt0 + q0w) * 1.0001f + 1e-6f;  // d^2 bound, fp slack
            float r21 = (wt1 + q1w) * 1.0001f + 1e-6f;
            float LBx = XMIN + blo * BW;
            float RBx = XMIN + (bhi + 1) * BW;
            if (leftOpen) {
                float gl0 = fmaxf(qx0 - LBx - SAFE, 0.0f);
                float gl1 = fmaxf(qx1 - LBx - SAFE, 0.0f);
                if (gl0 * gl0 >= r20 && gl1 * gl1 >= r21) leftOpen = false;
            }
            if (rightOpen) {
                float gr0 = fmaxf(RBx - qx0 - SAFE, 0.0f);
                float gr1 = fmaxf(RBx - qx1 - SAFE, 0.0f);
                if (gr0 * gr0 >= r20 && gr1 * gr1 >= r21) rightOpen = false;
            }
            if (!(leftOpen || rightOpen)) break;
            bool goLeft = (leftOpen && rightOpen) ? ((qx0 - LBx) < (RBx - qx1)) : leftOpen;
            if (goLeft) {
                blo--;
                process(off[blo], off[blo + 1]);
                leftOpen = blo > 0;
            } else {
                bhi++;
                process(off[bhi], off[bhi + 1]);
                rightOpen = bhi < NBUCK - 1;
            }
        }

        float l15 = __shfl_sync(FULLM, ld, 15);
        float l31 = __shfl_sync(FULLM, ld, 31);
        if (l15 != FLT_MAX && l31 != FLT_MAX) break;   // both lists full => exact
    }

    // epilogue: exact weight recomputation from coordinates (faithful to ref)
    float qx = -0.5f * (g ? a1x : a0x);
    float qy = -0.5f * (g ? a1y : a0y);
    float qz = -0.5f * (g ? a1z : a0z);
    const float4 nbp = rc[li];
    float dx = qx - nbp.x, dy = qy - nbp.y, dz = qz - nbp.z;
    float dist2 = fmaf(dx, dx, fmaf(dy, dy, dz * dz));
    float w = expf(-0.5f * dist2);

    const int qorig = rid[pos0 + g];
    const int qglob = bN + qorig;
    const int norig = rid[li];
    g_idx[qglob * KNN_K + sub] = norig;
    g_w [qglob * KNN_K + sub] = w;

    // reverse-degree scatter folded in (fixed-point => deterministic)
    unsigned long long inc = (unsigned long long)((double)w * 4294967296.0);
    atomicAdd(&g_Drev[bN + norig], inc);

    float s = w;
    s += __shfl_xor_sync(FULLM, s, 8);
    s += __shfl_xor_sync(FULLM, s, 4);
    s += __shfl_xor_sync(FULLM, s, 2);
    s += __shfl_xor_sync(FULLM, s, 1);
    if (sub == 0) g_Dfwd[qglob] = 0.5f * s;

    // ---- last KNN block to retire computes g_dis (hidden under fill) ----
    __threadfence();                           // publish Dfwd/Drev/idx/w
    __syncthreads();
    if (tid == 0) {
        int old = atomicAdd(&g_knn_done, 1);
        s_last = (old == nb_knn - 1) ? 1 : 0;
    }
    __syncthreads();
    if (s_last) {
        __threadfence();                       // acquire: all blocks' writes visible
        int total = B * N;
        for (int n = tid; n < total; n += TPB) {
            float D = g_Dfwd[n] + (float)((double)g_Drev[n] * (0.5 / 4294967296.0));
            g_dis[n] = 1.0f / sqrtf(fmaxf(D, 1e-6f));
        }
    }
}

// Sparse Laplacian scatter (+ flag resets for next graph replay).
__global__ void k_lap(float* __restrict__ out, int N, int total_edges)
{
    int e = blockIdx.x * blockDim.x + threadIdx.x;
    if (e == 0) { g_ready = 0; g_knn_done = 0; }   // stream-ordered: safe for replay
    if (e >= total_edges) return;
    int q = e >> 4;
    int b = q / N;
    int i = q - b * N;
    int j = g_idx[e];
    float w = g_w[e];

    float v = -((0.5f * w) * g_dis[q]) * g_dis[b * N + j];

    float* Lb = out + (size_t)b * N * (size_t)N;
    atomicAdd(Lb + (size_t)i * N + j, v);
    atomicAdd(Lb + (size_t)j * N + i, v);
}

extern "C" void kernel_launch(void* const* d_in, const int* in_sizes, int n_in,
                              void* d_out, int out_size)
{
    const float* xyz = (const float*)d_in[0];
    float* out = (float*)d_out;

    long long inel = in_sizes[0];                       // B*3*N
    int N = (int)((3LL * (long long)out_size) / inel);  // (3*B*N^2)/(3*B*N)
    int B = (int)(inel / (3LL * (long long)N));

    int nb_knn = B * (N / 64);        // 256 KNN blocks (64 queries each)
    int nb_ms  = 1792;                // grid-stride zero-fill blocks
    size_t smem = (size_t)N * sizeof(float4) + (size_t)N * sizeof(unsigned short)
                + (size_t)(NBUCK + 1) * sizeof(int);
    cudaFuncSetAttribute(k_fused, cudaFuncAttributeMaxDynamicSharedMemorySize, (int)smem);
    k_fused<<<B + nb_knn + nb_ms, TPB, smem>>>(xyz, out, N, B, nb_knn, nb_ms);

    int edges = B * N * KNN_K;
    int eb = (edges + 255) / 256;
    k_lap<<<eb, 256>>>(out, N, edges);
}

// round 15
// speedup vs baseline: 1.1378x; 1.1378x over previous
#include <cuda_runtime.h>
#include <math.h>
#include <float.h>

#define TPB    1024
#define KNN_K  16
#define NBUCK  64
#define FULLM  0xFFFFFFFFu
#define XMIN   (-4.8f)
#define XMAX   ( 4.8f)
#define BW     ((XMAX - XMIN) / (float)NBUCK)
#define INVBW  ((float)NBUCK / (XMAX - XMIN))
#define SAFE   1e-5f
#define FPRE   4          // rows each KNN block zero-fills before spinning

// scratch (static device arrays; allocation-free rule)
__device__ int                g_idx [65536 * KNN_K];
__device__ float              g_w   [65536 * KNN_K];
__device__ float              g_Dfwd[65536];
__device__ unsigned long long g_Drev[65536];
__device__ float              g_dis [65536];         // D^{-1/2} per node (k_dis)

__device__ int            g_off [16 * (NBUCK + 1)];
__device__ float4         g_rc  [65536];             // reordered (x,y,z,|p|^2)
__device__ unsigned short g_rid [65536];             // orig index per position
__device__ int            g_ready;                   // bucket-done counter (k_lap resets)

__device__ __forceinline__ int bucket_of_x(float x) {
    int ib = (int)((x - XMIN) * INVBW);
    return min(max(ib, 0), NBUCK - 1);
}

// zero one row + diagonal patch (lean streaming stores)
__device__ __forceinline__ void fill_row(float* __restrict__ out, int N, int r, int tid)
{
    const float4 z4 = make_float4(0.0f, 0.0f, 0.0f, 0.0f);
    int n4 = N >> 2;
    int b = r / N;
    int i = r - b * N;
    float4* row = reinterpret_cast<float4*>(out + ((size_t)b * N + i) * (size_t)N);
    #pragma unroll 2
    for (int f = tid; f < n4; f += TPB)
        __stcs(row + f, z4);
    int fd = i >> 2;
    if (tid == (fd & (TPB - 1))) {          // same thread re-writes same addr: ordered
        float4 v = z4;
        ((float*)&v)[i & 3] = 1.0f;
        __stcs(row + fd, v);
    }
}

// ---------- fused bucket + KNN + dense init (byte-identical to round 12) ----------
// bids [0, B):              bucket prepass (hist+scan+reorder+Drev zero), flag arrive
// bids [B, B+nb_knn):       KNN (prefill FPRE rows, spin on flag, then knn)
// bids [B+nb_knn, ...):     zero-fill remaining rows (grid-stride)
__global__ void __launch_bounds__(TPB, 2)
k_fused(const float* __restrict__ xyz, float* __restrict__ out,
        int N, int B, int nb_knn, int nb_ms)
{
    extern __shared__ char smraw[];
    const int tid = threadIdx.x;
    const int bid = blockIdx.x;

    if (bid < B) {
        // ---------------- bucket prepass (one batch per block) ------------
        int* h   = reinterpret_cast<int*>(smraw);
        int* cur = h + NBUCK;
        const int b = bid;
        const int bN = b * N;
        const float* X = xyz + (size_t)b * 3 * N;

        if (tid < NBUCK) h[tid] = 0;
        __syncthreads();
        for (int n = tid; n < N; n += TPB) {
            g_Drev[bN + n] = 0ull;          // pre-zero for knn epilogue atomics
            atomicAdd(&h[bucket_of_x(X[n])], 1);
        }
        __syncthreads();
        if (tid < 32) {                     // warp 0: scan 64 counts
            int v0 = h[tid], v1 = h[tid + 32];
            int s0 = v0, s1 = v1;
            for (int d = 1; d < 32; d <<= 1) {
                int t0 = __shfl_up_sync(FULLM, s0, d);
                int t1 = __shfl_up_sync(FULLM, s1, d);
                if (tid >= d) { s0 += t0; s1 += t1; }
            }
            s1 += __shfl_sync(FULLM, s0, 31);
            int ob = b * (NBUCK + 1);
            if (tid == 0) g_off[ob] = 0;
            g_off[ob + 1 + tid]  = s0;
            g_off[ob + 33 + tid] = s1;
            cur[tid]      = s0 - v0;
            cur[tid + 32] = s1 - v1;
        }
        __syncthreads();
        for (int n = tid; n < N; n += TPB) {
            float x = X[n], y = X[N + n], z = X[2 * N + n];
            float sq = fmaf(x, x, fmaf(y, y, z * z));
            int pos = atomicAdd(&cur[bucket_of_x(x)], 1);
            g_rc [bN + pos] = make_float4(x, y, z, sq);
            g_rid[bN + pos] = (unsigned short)n;
        }
        __threadfence();
        __syncthreads();
        if (tid == 0) atomicAdd(&g_ready, 1);
        return;
    }

    if (bid >= B + nb_knn) {
        // ------------- zero-fill remaining rows (grid-stride) -------------
        int msid  = bid - B - nb_knn;
        int nrows = B * N;
        for (int r = nb_knn * FPRE + msid; r < nrows; r += nb_ms)
            fill_row(out, N, r, tid);
        return;
    }

    // ---------------- KNN role ----------------
    const int kb = bid - B;                     // 0 .. nb_knn-1

    // useful work while bucket prepass runs: prefill FPRE rows
    for (int r = kb * FPRE; r < kb * FPRE + FPRE; r++)
        fill_row(out, N, r, tid);

    // wait for bucket flag (bucket blocks have lower bids => wave-1 resident)
    if (tid == 0) {
        while (atomicAdd(&g_ready, 0) < B) __nanosleep(64);
    }
    __syncthreads();
    __threadfence();

    float4*         rc  = reinterpret_cast<float4*>(smraw);            // N float4
    unsigned short* rid = reinterpret_cast<unsigned short*>(rc + N);   // N ushort
    int*            off = reinterpret_cast<int*>(rid + N);             // NBUCK+1

    const int qpb = (TPB / 32) * 2;             // 64 queries per block
    const int blocks_per_b = N / qpb;
    const int b = kb / blocks_per_b;
    const int qbase = (kb - b * blocks_per_b) * qpb;
    const int bN = b * N;

    for (int n = tid; n < N; n += TPB) rc[n]  = g_rc[bN + n];
    for (int n = tid; n < N; n += TPB) rid[n] = g_rid[bN + n];
    if (tid <= NBUCK) off[tid] = g_off[b * (NBUCK + 1) + tid];
    __syncthreads();

    const int warp = tid >> 5, lane = tid & 31;
    const int g = lane >> 4, sub = lane & 15;
    const int pos0 = qbase + warp * 2;          // bucket-sorted positions

    // queries kept ONLY in pre-scaled form to save registers: a = -2q, qw=|q|^2
    float a0x, a0y, a0z, q0w, a1x, a1y, a1z, q1w;
    {
        float4 q0 = rc[pos0];
        float4 q1 = rc[pos0 + 1];
        a0x = -2.0f * q0.x; a0y = -2.0f * q0.y; a0z = -2.0f * q0.z; q0w = q0.w;
        a1x = -2.0f * q1.x; a1y = -2.0f * q1.y; a1z = -2.0f * q1.z; q1w = q1.w;
    }

    // density-seeded screening thresholds in e-space (~40 expected pts in ball)
    const float seed0 = 0.1107f * __expf(q0w * (1.0f / 3.0f)) - q0w;
    const float seed1 = 0.1107f * __expf(q1w * (1.0f / 3.0f)) - q1w;

    // sorted-across-lanes top-16 in e-space; li = POSITION in rc
    float ld = FLT_MAX; int li = 0;
    float wt0, wt1;

    auto process = [&](int start, int end) {
        for (int p = start; p < end; p += 32) {
            int pp = p + lane;
            bool valid = pp < end;
            float4 c = rc[valid ? pp : end - 1];
            float e0 = fmaf(a0x, c.x, fmaf(a0y, c.y, fmaf(a0z, c.z, c.w)));
            float e1 = fmaf(a1x, c.x, fmaf(a1y, c.y, fmaf(a1z, c.z, c.w)));
            unsigned bal0 = __ballot_sync(FULLM, valid && (e0 < wt0));
            unsigned bal1 = __ballot_sync(FULLM, valid && (e1 < wt1));
            if ((bal0 | bal1) == 0u) continue;
            do {
                int s0 = __ffs(bal0) - 1;
                int s1 = __ffs(bal1) - 1;
                float dd0 = __shfl_sync(FULLM, e0, s0 & 31);
                float dd1 = __shfl_sync(FULLM, e1, s1 & 31);
                bool have = g ? (bal1 != 0u) : (bal0 != 0u);
                float dd = g ? dd1 : dd0;
                int   jj = p + ((g ? s1 : s0) & 31);
                bool pr = have && (dd < ld);
                unsigned pb = __ballot_sync(FULLM, pr);
                float sld = __shfl_up_sync(FULLM, ld, 1);
                int   sli = __shfl_up_sync(FULLM, li, 1);
                bool prevpr = (sub > 0) && ((pb >> (lane - 1)) & 1u);
                if (pr) { ld = prevpr ? sld : dd; li = prevpr ? sli : jj; }
                bal0 &= bal0 - 1;
                bal1 &= bal1 - 1;
            } while (bal0 | bal1);
            // monotone non-increasing thresholds (min with seed when underfull)
            wt0 = fminf(wt0, __shfl_sync(FULLM, ld, 15));
            wt1 = fminf(wt1, __shfl_sync(FULLM, ld, 31));
        }
    };

    // home buckets of the two queries (binary search over off[], warp-uniform)
    int hlo, hhi;
    {
        int lo = 0, hi = NBUCK - 1;
        while (lo < hi) { int mid = (lo + hi + 1) >> 1; if (off[mid] <= pos0) lo = mid; else hi = mid - 1; }
        hlo = lo;
        lo = hlo; hi = NBUCK - 1;
        int p1 = pos0 + 1;
        while (lo < hi) { int mid = (lo + hi + 1) >> 1; if (off[mid] <= p1) lo = mid; else hi = mid - 1; }
        hhi = lo;
    }

    for (int attempt = 0; attempt < 2; attempt++) {
        ld = FLT_MAX; li = 0;
        wt0 = attempt ? FLT_MAX : seed0;
        wt1 = attempt ? FLT_MAX : seed1;
        int blo = hlo, bhi = hhi;

        process(off[blo], off[bhi + 1]);

        bool leftOpen = blo > 0, rightOpen = bhi < NBUCK - 1;
        while (leftOpen || rightOpen) {
            float qx0 = -0.5f * a0x, qx1 = -0.5f * a1x;
            float r20 = (wt0 + q0w) * 1.0001f + 1e-6f;  // d^2 bound, fp slack
            float r21 = (wt1 + q1w) * 1.0001f + 1e-6f;
            float LBx = XMIN + blo * BW;
            float RBx = XMIN + (bhi + 1) * BW;
            if (leftOpen) {
                float gl0 = fmaxf(qx0 - LBx - SAFE, 0.0f);
                float gl1 = fmaxf(qx1 - LBx - SAFE, 0.0f);
                if (gl0 * gl0 >= r20 && gl1 * gl1 >= r21) leftOpen = false;
            }
            if (rightOpen) {
                float gr0 = fmaxf(RBx - qx0 - SAFE, 0.0f);
                float gr1 = fmaxf(RBx - qx1 - SAFE, 0.0f);
                if (gr0 * gr0 >= r20 && gr1 * gr1 >= r21) rightOpen = false;
            }
            if (!(leftOpen || rightOpen)) break;
            bool goLeft = (leftOpen && rightOpen) ? ((qx0 - LBx) < (RBx - qx1)) : leftOpen;
            if (goLeft) {
                blo--;
                process(off[blo], off[blo + 1]);
                leftOpen = blo > 0;
            } else {
                bhi++;
                process(off[bhi], off[bhi + 1]);
                rightOpen = bhi < NBUCK - 1;
            }
        }

        float l15 = __shfl_sync(FULLM, ld, 15);
        float l31 = __shfl_sync(FULLM, ld, 31);
        if (l15 != FLT_MAX && l31 != FLT_MAX) break;   // both lists full => exact
    }

    // epilogue: exact weight recomputation from coordinates (faithful to ref)
    float qx = -0.5f * (g ? a1x : a0x);
    float qy = -0.5f * (g ? a1y : a0y);
    float qz = -0.5f * (g ? a1z : a0z);
    const float4 nbp = rc[li];
    float dx = qx - nbp.x, dy = qy - nbp.y, dz = qz - nbp.z;
    float dist2 = fmaf(dx, dx, fmaf(dy, dy, dz * dz));
    float w = expf(-0.5f * dist2);

    const int qorig = rid[pos0 + g];
    const int qglob = bN + qorig;
    const int norig = rid[li];
    g_idx[qglob * KNN_K + sub] = norig;
    g_w [qglob * KNN_K + sub] = w;

    // reverse-degree scatter folded in (fixed-point => deterministic)
    unsigned long long inc = (unsigned long long)((double)w * 4294967296.0);
    atomicAdd(&g_Drev[bN + norig], inc);

    float s = w;
    s += __shfl_xor_sync(FULLM, s, 8);
    s += __shfl_xor_sync(FULLM, s, 4);
    s += __shfl_xor_sync(FULLM, s, 2);
    s += __shfl_xor_sync(FULLM, s, 1);
    if (sub == 0) g_Dfwd[qglob] = 0.5f * s;
}

// ---------- per-node D^{-1/2} (same combine/order as round-12 inline) ----------
__global__ void k_dis(int total)
{
    int n = blockIdx.x * blockDim.x + threadIdx.x;
    if (n >= total) return;
    float D = g_Dfwd[n] + (float)((double)g_Drev[n] * (0.5 / 4294967296.0));
    g_dis[n] = 1.0f / sqrtf(fmaxf(D, 1e-6f));
}

// ---------- lean sparse Laplacian scatter (2 edges/thread for MLP) ----------
__global__ void k_lap(float* __restrict__ out, int N, int total_edges)
{
    int t = blockIdx.x * blockDim.x + threadIdx.x;
    if (t == 0) g_ready = 0;                // stream-ordered: safe for next replay
    #pragma unroll
    for (int k = 0; k < 2; k++) {
        int e = t * 2 + k;
        if (e >= total_edges) return;
        int q = e >> 4;
        int b = q / N;
        int i = q - b * N;
        int j = __ldg(&g_idx[e]);
        float w = __ldg(&g_w[e]);
        float v = -((0.5f * w) * __ldg(&g_dis[q])) * __ldg(&g_dis[b * N + j]);
        float* Lb = out + (size_t)b * N * (size_t)N;
        atomicAdd(Lb + (size_t)i * N + j, v);
        atomicAdd(Lb + (size_t)j * N + i, v);
    }
}

extern "C" void kernel_launch(void* const* d_in, const int* in_sizes, int n_in,
                              void* d_out, int out_size)
{
    const float* xyz = (const float*)d_in[0];
    float* out = (float*)d_out;

    long long inel = in_sizes[0];                       // B*3*N
    int N = (int)((3LL * (long long)out_size) / inel);  // (3*B*N^2)/(3*B*N)
    int B = (int)(inel / (3LL * (long long)N));

    int nb_knn = B * (N / 64);        // 256 KNN blocks (64 queries each)
    int nb_ms  = 1792;                // grid-stride zero-fill blocks
    size_t smem = (size_t)N * sizeof(float4) + (size_t)N * sizeof(unsigned short)
                + (size_t)(NBUCK + 1) * sizeof(int);
    cudaFuncSetAttribute(k_fused, cudaFuncAttributeMaxDynamicSharedMemorySize, (int)smem);
    k_fused<<<B + nb_knn + nb_ms, TPB, smem>>>(xyz, out, N, B, nb_knn, nb_ms);

    int nodes = B * N;
    k_dis<<<(nodes + 255) / 256, 256>>>(nodes);

    int edges = B * N * KNN_K;
    int eb = (edges / 2 + 255) / 256;
    k_lap<<<eb, 256>>>(out, N, edges);
}